// round 10
// baseline (speedup 1.0000x reference)
#include <cuda_runtime.h>

// EPN layer, i-pair blocking: each block handles (b, i0=2p, i1=2p+1) x 96 j-edges.
// Every weight LDS broadcast (w2d, w1c2, u/v) is amortized over 2 edges; the
// G[k][j] global load is shared between the two edges (same j).
// Directions (ij, ji) packed into f32x2 lanes as before.

#define NB 32
#define NN 96
#define NNODE (NB*NN)

typedef unsigned long long u64;

__device__ float2 g_G[NB * 32 * NN];   // [b][k][n] = {T[b,n,k], S[b,n,k]}

__device__ __forceinline__ u64 pack2(float lo, float hi) {
    u64 r; asm("mov.b64 %0, {%1, %2};" : "=l"(r) : "f"(lo), "f"(hi)); return r;
}
__device__ __forceinline__ void unpack2(u64 v, float& lo, float& hi) {
    asm("mov.b64 {%0, %1}, %2;" : "=f"(lo), "=f"(hi) : "l"(v));
}
__device__ __forceinline__ u64 fma2(u64 a, u64 b, u64 c) {
    u64 d; asm("fma.rn.f32x2 %0, %1, %2, %3;" : "=l"(d) : "l"(a), "l"(b), "l"(c)); return d;
}

// ---------------- precompute S/T per node ----------------
__global__ void epn_prep_kernel(const float* __restrict__ h,
                                const float* __restrict__ q,
                                const float* __restrict__ W1) {
    int node = blockIdx.x;               // 0..3071
    __shared__ float x[65];
    int t = threadIdx.x;                 // block = 64
    if (t < 64) x[t] = h[node * 64 + t];
    if (t == 0) x[64] = q[node];
    __syncthreads();
    if (t < 32) {
        float s = 0.f, tt = 0.f;
        #pragma unroll
        for (int d = 0; d < 65; d++) {
            float xv = x[d];
            s  = fmaf(xv, W1[d * 32 + t], s);          // W1a column t
            tt = fmaf(xv, W1[(65 + d) * 32 + t], tt);  // W1b column t
        }
        int b = node / NN, n = node % NN;
        g_G[(b * 32 + t) * NN + n] = make_float2(tt, s);
    }
}

// ---------------- main kernel: block = (b, i-pair), thread = j ----------------
__global__ void __launch_bounds__(96, 2)
epn_main_kernel(const float* __restrict__ e,
                const float* __restrict__ q,
                const float* __restrict__ mask,
                const float* __restrict__ W1,
                const float* __restrict__ b1,
                const float* __restrict__ W2,
                const float* __restrict__ b2,
                const float* __restrict__ W3,
                float* __restrict__ out) {
    int bx = blockIdx.x;            // 0..1535
    int b  = bx / (NN / 2);
    int ip = bx % (NN / 2);
    int i0 = ip * 2, i1 = ip * 2 + 1;
    int t  = threadIdx.x;           // j = 0..95

    __shared__ u64   w2d[32][32];   // duplicated W2 pairs (8KB)
    __shared__ u64   w1c2[16][16];  // W1c hidden-unit pairs (2KB)
    __shared__ float uA[32], vA[32];// S_i0+b1, T_i0+b1
    __shared__ float uB[32], vB[32];// S_i1+b1, T_i1+b1
    __shared__ float w3_sh[32];
    __shared__ u64   b2d[32];
    __shared__ float redA[3], redB[3];

    // ---- stage weights ----
    for (int idx = t; idx < 1024; idx += 96) {
        float w = W2[idx];
        w2d[idx >> 5][idx & 31] = pack2(w, w);
    }
    for (int idx = t; idx < 256; idx += 96) {
        int d = idx >> 4, p = idx & 15;
        float2 w = ((const float2*)(W1 + (130 + d) * 32))[p];
        w1c2[d][p] = pack2(w.x, w.y);
    }
    if (t < 32) {
        float bb = b1[t];
        float2 gA = g_G[(b * 32 + t) * NN + i0];
        float2 gB = g_G[(b * 32 + t) * NN + i1];
        uA[t] = gA.y + bb;  vA[t] = gA.x + bb;
        uB[t] = gB.y + bb;  vB[t] = gB.x + bb;
        w3_sh[t] = W3[t];
        float bv = b2[t];
        b2d[t]   = pack2(bv, bv);
    }
    __syncthreads();

    // ---- e rows for both edges ----
    const float4* evA = (const float4*)(e + ((size_t)(b * NN + i0) * NN + t) * 16);
    const float4* evB = (const float4*)(e + ((size_t)(b * NN + i1) * NN + t) * 16);
    float edA[16], edB[16];
    #pragma unroll
    for (int v = 0; v < 4; v++) {
        float4 a = evA[v];
        edA[4*v] = a.x; edA[4*v+1] = a.y; edA[4*v+2] = a.z; edA[4*v+3] = a.w;
        float4 c = evB[v];
        edB[4*v] = c.x; edB[4*v+1] = c.y; edB[4*v+2] = c.z; edB[4*v+3] = c.w;
    }

    // ---- c = e @ W1c for both edges, packed over hidden-unit pairs ----
    u64 c2A[16], c2B[16];
    #pragma unroll
    for (int p = 0; p < 16; p++) { c2A[p] = 0ull; c2B[p] = 0ull; }
    #pragma unroll
    for (int d = 0; d < 16; d++) {
        u64 ea = pack2(edA[d], edA[d]);
        u64 eb = pack2(edB[d], edB[d]);
        #pragma unroll
        for (int p = 0; p < 16; p++) {
            u64 w = w1c2[d][p];         // one LDS serves both edges
            c2A[p] = fma2(ea, w, c2A[p]);
            c2B[p] = fma2(eb, w, c2B[p]);
        }
    }

    // ---- layer1: zp[k] = {relu(c+u+T_j), relu(c+v+S_j)} per edge ----
    const float2* Gb = g_G + (size_t)b * 32 * NN;
    u64 zpA[32], zpB[32];
    #pragma unroll
    for (int p = 0; p < 16; p++) {
        float cA0, cA1, cB0, cB1;
        unpack2(c2A[p], cA0, cA1);
        unpack2(c2B[p], cB0, cB1);
        {
            int k = 2 * p;
            float2 g = Gb[k * NN + t];        // shared by both edges (same j)
            zpA[k] = pack2(fmaxf(cA0 + uA[k] + g.x, 0.f),
                           fmaxf(cA0 + vA[k] + g.y, 0.f));
            zpB[k] = pack2(fmaxf(cB0 + uB[k] + g.x, 0.f),
                           fmaxf(cB0 + vB[k] + g.y, 0.f));
        }
        {
            int k = 2 * p + 1;
            float2 g = Gb[k * NN + t];
            zpA[k] = pack2(fmaxf(cA1 + uA[k] + g.x, 0.f),
                           fmaxf(cA1 + vA[k] + g.y, 0.f));
            zpB[k] = pack2(fmaxf(cB1 + uB[k] + g.x, 0.f),
                           fmaxf(cB1 + vB[k] + g.y, 0.f));
        }
    }

    // ---- layer2 (32x32) + relu + layer3, both edges share every weight LDS ----
    float oijA = 0.f, ojiA = 0.f, oijB = 0.f, ojiB = 0.f;
    #pragma unroll
    for (int tile = 0; tile < 4; tile++) {
        u64 accA[8], accB[8];
        #pragma unroll
        for (int o = 0; o < 8; o++) {
            u64 bv = b2d[tile * 8 + o];
            accA[o] = bv; accB[o] = bv;
        }
        #pragma unroll
        for (int ki = 0; ki < 32; ki++) {
            u64 zA = zpA[ki], zB = zpB[ki];
            #pragma unroll
            for (int o = 0; o < 8; o++) {
                u64 w = w2d[ki][tile * 8 + o];   // one LDS, two FFMA2
                accA[o] = fma2(zA, w, accA[o]);
                accB[o] = fma2(zB, w, accB[o]);
            }
        }
        #pragma unroll
        for (int o = 0; o < 8; o++) {
            float w3v = w3_sh[tile * 8 + o];
            float lo, hi;
            unpack2(accA[o], lo, hi);
            oijA = fmaf(fmaxf(lo, 0.f), w3v, oijA);
            ojiA = fmaf(fmaxf(hi, 0.f), w3v, ojiA);
            unpack2(accB[o], lo, hi);
            oijB = fmaf(fmaxf(lo, 0.f), w3v, oijB);
            ojiB = fmaf(fmaxf(hi, 0.f), w3v, ojiB);
        }
    }

    // ---- antisymmetrize + block reduce over j, for both edges ----
    float rA = (oijA - ojiA) * mask[(size_t)(b * NN + i0) * NN + t];
    float rB = (oijB - ojiB) * mask[(size_t)(b * NN + i1) * NN + t];
    #pragma unroll
    for (int off = 16; off > 0; off >>= 1) {
        rA += __shfl_down_sync(0xffffffffu, rA, off);
        rB += __shfl_down_sync(0xffffffffu, rB, off);
    }
    if ((t & 31) == 0) { redA[t >> 5] = rA; redB[t >> 5] = rB; }
    __syncthreads();
    if (t == 0) {
        out[b * NN + i0] = q[b * NN + i0] + redA[0] + redA[1] + redA[2];
        out[b * NN + i1] = q[b * NN + i1] + redB[0] + redB[1] + redB[2];
    }
}

extern "C" void kernel_launch(void* const* d_in, const int* in_sizes, int n_in,
                              void* d_out, int out_size) {
    const float* h    = (const float*)d_in[0];
    const float* e    = (const float*)d_in[1];
    const float* q    = (const float*)d_in[2];
    const float* mask = (const float*)d_in[3];
    const float* W1   = (const float*)d_in[4];
    const float* b1   = (const float*)d_in[5];
    const float* W2   = (const float*)d_in[6];
    const float* b2   = (const float*)d_in[7];
    const float* W3   = (const float*)d_in[8];
    // d_in[9] = b3 cancels in the antisymmetric difference
    float* out = (float*)d_out;

    epn_prep_kernel<<<NNODE, 64>>>(h, q, W1);
    epn_main_kernel<<<NB * (NN / 2), 96>>>(e, q, mask, W1, b1, W2, b2, W3, out);
}

// round 11
// speedup vs baseline: 1.0238x; 1.0238x over previous
#include <cuda_runtime.h>

// EPN layer. Layer1 decomposition: pre_ij = S_i + T_j + (e_ij @ W1c) + b1.
// Directions (ij, ji) packed in f32x2. Layer1->layer2 fused per hidden unit k:
// z[k] is consumed into 32 packed accumulators immediately (no zp[] array),
// weight reads are LDS.128 (2 FFMA2 per LDS), z-stage adds are packed add.f32x2.

#define NB 32
#define NN 96
#define NNODE (NB*NN)

typedef unsigned long long u64;

__device__ float2 g_G[NB * 32 * NN];   // [b][k][n] = {T[b,n,k], S[b,n,k]}

__device__ __forceinline__ u64 pack2(float lo, float hi) {
    u64 r; asm("mov.b64 %0, {%1, %2};" : "=l"(r) : "f"(lo), "f"(hi)); return r;
}
__device__ __forceinline__ void unpack2(u64 v, float& lo, float& hi) {
    asm("mov.b64 {%0, %1}, %2;" : "=f"(lo), "=f"(hi) : "l"(v));
}
__device__ __forceinline__ u64 fma2(u64 a, u64 b, u64 c) {
    u64 d; asm("fma.rn.f32x2 %0, %1, %2, %3;" : "=l"(d) : "l"(a), "l"(b), "l"(c)); return d;
}
__device__ __forceinline__ u64 add2(u64 a, u64 b) {
    u64 d; asm("add.rn.f32x2 %0, %1, %2;" : "=l"(d) : "l"(a), "l"(b)); return d;
}

// ---------------- precompute S/T per node ----------------
__global__ void epn_prep_kernel(const float* __restrict__ h,
                                const float* __restrict__ q,
                                const float* __restrict__ W1) {
    int node = blockIdx.x;               // 0..3071
    __shared__ float x[65];
    int t = threadIdx.x;                 // block = 64
    if (t < 64) x[t] = h[node * 64 + t];
    if (t == 0) x[64] = q[node];
    __syncthreads();
    if (t < 32) {
        float s = 0.f, tt = 0.f;
        #pragma unroll
        for (int d = 0; d < 65; d++) {
            float xv = x[d];
            s  = fmaf(xv, W1[d * 32 + t], s);          // W1a column t
            tt = fmaf(xv, W1[(65 + d) * 32 + t], tt);  // W1b column t
        }
        int b = node / NN, n = node % NN;
        g_G[(b * 32 + t) * NN + n] = make_float2(tt, s);
    }
}

// ---------------- main kernel: block = (b,i), thread = j ----------------
__global__ void __launch_bounds__(96, 4)
epn_main_kernel(const float* __restrict__ e,
                const float* __restrict__ q,
                const float* __restrict__ mask,
                const float* __restrict__ W1,
                const float* __restrict__ b1,
                const float* __restrict__ W2,
                const float* __restrict__ b2,
                const float* __restrict__ W3,
                float* __restrict__ out) {
    int bi = blockIdx.x;            // 0..3071 : (b,i)
    int b  = bi / NN;
    int i  = bi % NN;
    int t  = threadIdx.x;           // j = 0..95

    __shared__ u64   w2d[32][32];   // duplicated W2[ki][ko] pairs, 256B rows (8KB)
    __shared__ u64   w1c2[16][16];  // {W1c[d][2p], W1c[d][2p+1]} (2KB)
    __shared__ u64   uv[32];        // {S_i[k]+b1[k], T_i[k]+b1[k]}
    __shared__ float w3_sh[32];
    __shared__ u64   b2d[32];       // {b2[o], b2[o]}
    __shared__ float red[3];

    // ---- stage weights ----
    for (int idx = t; idx < 1024; idx += 96) {
        float w = W2[idx];
        w2d[idx >> 5][idx & 31] = pack2(w, w);
    }
    for (int idx = t; idx < 256; idx += 96) {
        int d = idx >> 4, p = idx & 15;
        float2 w = ((const float2*)(W1 + (130 + d) * 32))[p];
        w1c2[d][p] = pack2(w.x, w.y);
    }
    if (t < 32) {
        float2 g = g_G[(b * 32 + t) * NN + i];
        float bb = b1[t];
        uv[t] = pack2(g.y + bb, g.x + bb);   // {S_i+b1, T_i+b1}
        w3_sh[t] = W3[t];
        float bv = b2[t];
        b2d[t]   = pack2(bv, bv);
    }
    __syncthreads();

    // ---- per-edge e row (16 floats) ----
    const float4* ev4 = (const float4*)(e + ((size_t)bi * NN + t) * 16);
    float ed[16];
    #pragma unroll
    for (int v = 0; v < 4; v++) {
        float4 a = ev4[v];
        ed[4*v] = a.x; ed[4*v+1] = a.y; ed[4*v+2] = a.z; ed[4*v+3] = a.w;
    }

    // ---- c = e @ W1c, packed over hidden-unit pairs, LDS.128 weights ----
    u64 c2[16];
    #pragma unroll
    for (int p = 0; p < 16; p++) c2[p] = 0ull;
    #pragma unroll
    for (int d = 0; d < 16; d++) {
        u64 edup = pack2(ed[d], ed[d]);
        #pragma unroll
        for (int p2 = 0; p2 < 8; p2++) {
            ulonglong2 w = *(const ulonglong2*)&w1c2[d][p2 * 2];
            c2[2*p2]     = fma2(edup, w.x, c2[2*p2]);
            c2[2*p2 + 1] = fma2(edup, w.y, c2[2*p2 + 1]);
        }
    }

    // ---- fused layer1 -> layer2: per k, make z then feed 32 packed accs ----
    u64 acc[32];
    #pragma unroll
    for (int o2 = 0; o2 < 16; o2++) {
        ulonglong2 bv = *(const ulonglong2*)&b2d[o2 * 2];
        acc[2*o2] = bv.x; acc[2*o2 + 1] = bv.y;
    }

    const float2* Gb = g_G + (size_t)b * 32 * NN;
    #pragma unroll
    for (int p = 0; p < 16; p++) {
        float c0, c1;
        unpack2(c2[p], c0, c1);
        #pragma unroll
        for (int s = 0; s < 2; s++) {
            int k = 2 * p + s;
            float ck = s ? c1 : c0;
            float2 g = Gb[k * NN + t];               // {T_j[k], S_j[k]} coalesced LDG.64
            u64 pre = add2(add2(pack2(ck, ck), uv[k]), pack2(g.x, g.y));
            float pl, ph;
            unpack2(pre, pl, ph);
            u64 z = pack2(fmaxf(pl, 0.f), fmaxf(ph, 0.f));   // {z_ij[k], z_ji[k]}
            #pragma unroll
            for (int o2 = 0; o2 < 16; o2++) {
                ulonglong2 w = *(const ulonglong2*)&w2d[k][o2 * 2];  // LDS.128, 2 FFMA2
                acc[2*o2]     = fma2(z, w.x, acc[2*o2]);
                acc[2*o2 + 1] = fma2(z, w.y, acc[2*o2 + 1]);
            }
        }
    }

    // ---- relu + layer3 ----
    float oij = 0.f, oji = 0.f;
    #pragma unroll
    for (int o = 0; o < 32; o++) {
        float lo, hi;
        unpack2(acc[o], lo, hi);
        float w3v = w3_sh[o];
        oij = fmaf(fmaxf(lo, 0.f), w3v, oij);
        oji = fmaf(fmaxf(hi, 0.f), w3v, oji);
    }

    // ---- antisymmetrize + block reduce over j ----
    float r = (oij - oji) * mask[(size_t)bi * NN + t];
    #pragma unroll
    for (int off = 16; off > 0; off >>= 1)
        r += __shfl_down_sync(0xffffffffu, r, off);
    if ((t & 31) == 0) red[t >> 5] = r;
    __syncthreads();
    if (t == 0) out[bi] = q[bi] + red[0] + red[1] + red[2];
}

extern "C" void kernel_launch(void* const* d_in, const int* in_sizes, int n_in,
                              void* d_out, int out_size) {
    const float* h    = (const float*)d_in[0];
    const float* e    = (const float*)d_in[1];
    const float* q    = (const float*)d_in[2];
    const float* mask = (const float*)d_in[3];
    const float* W1   = (const float*)d_in[4];
    const float* b1   = (const float*)d_in[5];
    const float* W2   = (const float*)d_in[6];
    const float* b2   = (const float*)d_in[7];
    const float* W3   = (const float*)d_in[8];
    // d_in[9] = b3 cancels in the antisymmetric difference
    float* out = (float*)d_out;

    epn_prep_kernel<<<NNODE, 64>>>(h, q, W1);
    epn_main_kernel<<<NNODE, 96>>>(e, q, mask, W1, b1, W2, b2, W3, out);
}